// round 10
// baseline (speedup 1.0000x reference)
#include <cuda_runtime.h>
#include <cuda_pipeline.h>

// Mat2Twist: rotation matrix (3x3) -> axis-angle (3). Memory-bound.
//
// R8: double-buffered cp.async pipeline over 256-matrix tiles.
//   - R7's tile shape (best measured DRAM%) kept per stage
//   - cp.async.cg 16B staging: next tile's loads overlap current tile's
//     compute+store, so the CTA never stops issuing global reads
//   - grid-stride loop, grid = 148*8 CTAs, smem 24.6KB (8 CTAs/SM)
//   - __stcs streaming stores (output is touch-once)

#define TPB  256
#define MATS 256
#define F4T  ((MATS * 9) / 4)   // 576 float4 per tile

__global__ __launch_bounds__(TPB) void mat2twist_kernel(
    const float* __restrict__ in, float* __restrict__ out,
    int n, int nFullTiles)
{
    __shared__ float4 s_in[2][F4T];          // 2 * 9216 B
    __shared__ float  s_out[2][MATS * 3];    // 2 * 3072 B

    const int tid = threadIdx.x;
    const float4* __restrict__ gin4 = reinterpret_cast<const float4*>(in);

    // ---- prefetch first tile ----
    int tile = blockIdx.x;
    if (tile < nFullTiles) {
        const float4* src = gin4 + (size_t)tile * F4T;
        __pipeline_memcpy_async(&s_in[0][tid],           src + tid,           16);
        __pipeline_memcpy_async(&s_in[0][tid + TPB],     src + tid + TPB,     16);
        if (tid < F4T - 2 * TPB)
            __pipeline_memcpy_async(&s_in[0][tid + 2 * TPB], src + tid + 2 * TPB, 16);
    }
    __pipeline_commit();

    int buf = 0;
    for (; tile < nFullTiles; tile += gridDim.x) {
        // ---- prefetch next tile into other buffer ----
        int next = tile + gridDim.x;
        if (next < nFullTiles) {
            const float4* src = gin4 + (size_t)next * F4T;
            int nb = buf ^ 1;
            __pipeline_memcpy_async(&s_in[nb][tid],           src + tid,           16);
            __pipeline_memcpy_async(&s_in[nb][tid + TPB],     src + tid + TPB,     16);
            if (tid < F4T - 2 * TPB)
                __pipeline_memcpy_async(&s_in[nb][tid + 2 * TPB], src + tid + 2 * TPB, 16);
        }
        __pipeline_commit();             // commit (possibly empty) group
        __pipeline_wait_prior(1);        // current tile's group done
        __syncthreads();

        // ---- compute current tile ----
        const float* m = reinterpret_cast<const float*>(s_in[buf]) + tid * 9;
        float m00 = m[0], m01 = m[1], m02 = m[2];
        float m10 = m[3], m11 = m[4], m12 = m[5];
        float m20 = m[6], m21 = m[7], m22 = m[8];

        float c = 0.5f * (m00 + m11 + m22 - 1.0f);
        c = fminf(1.0f, fmaxf(-1.0f, c));
        // sin(acos(c)) = sqrt(1-c^2); theta in [0.1, pi-0.1] keeps this safe
        float scale = 0.5f * acosf(c) * rsqrtf(fmaxf(1.0f - c * c, 1e-12f));

        s_out[buf][tid * 3 + 0] = scale * (m21 - m12);
        s_out[buf][tid * 3 + 1] = scale * (m02 - m20);
        s_out[buf][tid * 3 + 2] = scale * (m10 - m01);
        __syncthreads();

        // ---- coalesced store: 192 float4 ----
        float4* __restrict__ gout =
            reinterpret_cast<float4*>(out + (size_t)tile * MATS * 3);
        const float4* so4 = reinterpret_cast<const float4*>(s_out[buf]);
        if (tid < (MATS * 3) / 4)
            __stcs(gout + tid, so4[tid]);

        buf ^= 1;
    }

    // ---- tail: matrices beyond the last full tile (scalar) ----
    int tailStart = nFullTiles * MATS;
    for (int i = tailStart + blockIdx.x * TPB + tid; i < n;
         i += gridDim.x * TPB) {
        const float* m = in + (size_t)i * 9;
        float m00 = m[0], m01 = m[1], m02 = m[2];
        float m10 = m[3], m11 = m[4], m12 = m[5];
        float m20 = m[6], m21 = m[7], m22 = m[8];

        float c = 0.5f * (m00 + m11 + m22 - 1.0f);
        c = fminf(1.0f, fmaxf(-1.0f, c));
        float scale = 0.5f * acosf(c) * rsqrtf(fmaxf(1.0f - c * c, 1e-12f));

        out[(size_t)i * 3 + 0] = scale * (m21 - m12);
        out[(size_t)i * 3 + 1] = scale * (m02 - m20);
        out[(size_t)i * 3 + 2] = scale * (m10 - m01);
    }
}

extern "C" void kernel_launch(void* const* d_in, const int* in_sizes, int n_in,
                              void* d_out, int out_size)
{
    const float* in = (const float*)d_in[0];
    float* out = (float*)d_out;
    int n = in_sizes[0] / 9;            // number of matrices
    int nFullTiles = n / MATS;

    int grid = 148 * 8;                  // 8 CTAs/SM (smem+thread limit)
    int maxUseful = nFullTiles > 0 ? nFullTiles : 1;
    if (grid > maxUseful) grid = maxUseful;

    mat2twist_kernel<<<grid, TPB>>>(in, out, n, nFullTiles);
}